// round 14
// baseline (speedup 1.0000x reference)
#include <cuda_runtime.h>
#include <cuda_bf16.h>
#include <math.h>

// ---------------- problem constants ----------------
#define NC      21
#define MEM     1000
#define DIM     128
#define NPIX    131072      // 8 * 128 * 128
#define K_EASY  39          // int(200 * (1 - 0.8)) with fp64 rounding
#define K_HARD  160
#define AA      199         // K_EASY + K_HARD
#define NROWS   20000       // (NC-1) * MEM
#define NPAD    20096       // 157 * 128
#define MPAD    256
#define MARGIN  0.2f
#define NEGS    (NROWS - MEM)   // 19000
#define CAP     6144
#define TS      512             // k_select threads

// ---------------- scratch (device globals; no allocation allowed) --------
__device__ __align__(16) unsigned char g_sw[NPIX];
__device__ __align__(16) unsigned char g_sp[NPIX];
__device__ __align__(16) unsigned char g_fg[NPIX];
__device__ int           g_cls;
__device__ int           g_idx[AA];
__device__ unsigned char g_valid[AA];
__device__ int           g_ne, g_nh, g_nv;
__device__ int           g_done;
__device__ float         g_anchors[MPAD * DIM];
__device__ float         g_sims[MPAD * NPAD];
__device__ double        g_loss;

// ---------------- helpers ----------------
__device__ __forceinline__ unsigned fmono(float f) {
    unsigned u = __float_as_uint(f);
    return (u & 0x80000000u) ? ~u : (u | 0x80000000u);
}
__device__ __forceinline__ float fmono_inv(unsigned u) {
    return (u & 0x80000000u) ? __uint_as_float(u & 0x7FFFFFFFu)
                             : __uint_as_float(~u);
}

// block-wide EXCLUSIVE scans (two-level shuffle), for TS=512 (16 warps)
__device__ __forceinline__ unsigned blk_exscan_u(unsigned v, int tid, unsigned* wb) {
    __syncthreads();                       // protect wb reuse
    int lane = tid & 31, wid = tid >> 5;
    unsigned x = v;
#pragma unroll
    for (int o = 1; o < 32; o <<= 1) {
        unsigned t = __shfl_up_sync(0xffffffffu, x, o);
        if (lane >= o) x += t;
    }
    if (lane == 31) wb[wid] = x;
    __syncthreads();
    if (tid < 16) {
        unsigned w = wb[tid];
#pragma unroll
        for (int o = 1; o < 16; o <<= 1) {
            unsigned t = __shfl_up_sync(0x0000ffffu, w, o);
            if (tid >= o) w += t;
        }
        wb[tid] = w;
    }
    __syncthreads();
    unsigned off = (wid > 0) ? wb[wid - 1] : 0u;
    return off + x - v;
}
__device__ __forceinline__ double blk_exscan_d(double v, int tid, double* wb) {
    __syncthreads();
    int lane = tid & 31, wid = tid >> 5;
    double x = v;
#pragma unroll
    for (int o = 1; o < 32; o <<= 1) {
        double t = __shfl_up_sync(0xffffffffu, x, o);
        if (lane >= o) x += t;
    }
    if (lane == 31) wb[wid] = x;
    __syncthreads();
    if (tid < 16) {
        double w = wb[tid];
#pragma unroll
        for (int o = 1; o < 16; o <<= 1) {
            double t = __shfl_up_sync(0x0000ffffu, w, o);
            if (tid >= o) w += t;
        }
        wb[tid] = w;
    }
    __syncthreads();
    double off = (wid > 0) ? wb[wid - 1] : 0.0;
    return off + x - v;
}

// ---------------- kernel 1: labels + pred argmax (512 blocks only) ---------
__global__ void k_prep(const float* __restrict__ preds,
                       const int* __restrict__ wsss,
                       const int* __restrict__ fsss) {
    int bid = blockIdx.x;
    int tid = threadIdx.x;
    int n = bid * 256 + tid;
    int b = n >> 14;
    int rem = n & 16383;
    int y = rem >> 7;
    int x = rem & 127;
    int Y = y * 4, X = x * 4;
    int gidx = (b * 512 + Y) * 512 + X;
    int sw = wsss[gidx];
    int sf = fsss[gidx];

    const float* p = preds + ((long long)b * NC) * 262144 + (long long)Y * 512 + X;
    float best = __ldg(p);
    int bi = 0;
#pragma unroll
    for (int c = 1; c < NC; c++) {
        float v = __ldg(p + (long long)c * 262144);
        if (v > best) { best = v; bi = c; }
    }
    g_sw[n] = (unsigned char)sw;
    g_sp[n] = (unsigned char)bi;
    g_fg[n] = (unsigned char)((sf != 0) && (sf != 255));
}

// ---------------- kernel 2: cls + ordered pick (vector loads, shuffle scan) -
__global__ void k_pick() {
    const int T = 1024, P = 4, CH = T * P;   // 4096 pixels per chunk
    __shared__ int wbE[32], wbH[32];
    __shared__ int baseE, baseH;
    __shared__ int s_cls;
    int tid = threadIdx.x;
    int lane = tid & 31, wid = tid >> 5;
    if (tid == 0) { baseE = 0; baseH = 0; s_cls = 255; g_loss = 0.0; g_done = 0; }
    __syncthreads();

    // phase A: min valid label over g_sw
    {
        const uint4* sw4 = reinterpret_cast<const uint4*>(g_sw);
        unsigned m4 = 0xFFFFFFFFu;
#pragma unroll
        for (int q = 0; q < 8; q++) {
            uint4 v = sw4[tid * 8 + q];
            unsigned a = v.x | __vcmpeq4(v.x, 0u);
            unsigned b = v.y | __vcmpeq4(v.y, 0u);
            unsigned c = v.z | __vcmpeq4(v.z, 0u);
            unsigned d = v.w | __vcmpeq4(v.w, 0u);
            m4 = __vminu4(m4, __vminu4(__vminu4(a, b), __vminu4(c, d)));
        }
        unsigned m = min(min(m4 & 255u, (m4 >> 8) & 255u),
                         min((m4 >> 16) & 255u, (m4 >> 24) & 255u));
        for (int off = 16; off; off >>= 1)
            m = min(m, __shfl_down_sync(0xffffffffu, m, off));
        if (lane == 0) atomicMin(&s_cls, (int)m);
    }
    __syncthreads();
    int cls = (s_cls <= NC - 1) ? s_cls : NC;
    if (tid == 0) g_cls = cls;
    unsigned cls4 = (unsigned)cls * 0x01010101u;
    const unsigned one4 = 0x01010101u;

    // phase B: ordered pick, 4 pixels per thread per chunk via uint loads
    for (int start = 0; start < NPIX; start += CH) {
        int bE = baseE, bH = baseH;
        int widx = (start >> 2) + tid;
        unsigned sw = reinterpret_cast<const unsigned*>(g_sw)[widx];
        unsigned sp = reinterpret_cast<const unsigned*>(g_sp)[widx];
        unsigned fg = reinterpret_cast<const unsigned*>(g_fg)[widx];
        unsigned ancm = __vcmpeq4(sw, cls4) & __vcmpeq4(fg, one4);
        unsigned spm  = __vcmpeq4(sp, cls4);
        unsigned em = ancm & spm;
        unsigned hm = ancm & ~spm;
        int cE = __popc(em) >> 3;
        int cH = __popc(hm) >> 3;

        int xE = cE, xH = cH;
#pragma unroll
        for (int o = 1; o < 32; o <<= 1) {
            int tE = __shfl_up_sync(0xffffffffu, xE, o);
            int tH = __shfl_up_sync(0xffffffffu, xH, o);
            if (lane >= o) { xE += tE; xH += tH; }
        }
        if (lane == 31) { wbE[wid] = xE; wbH[wid] = xH; }
        __syncthreads();
        if (wid == 0) {
            int w = wbE[lane];
#pragma unroll
            for (int o = 1; o < 32; o <<= 1) {
                int t2 = __shfl_up_sync(0xffffffffu, w, o);
                if (lane >= o) w += t2;
            }
            wbE[lane] = w;
        } else if (wid == 1) {
            int w = wbH[lane];
#pragma unroll
            for (int o = 1; o < 32; o <<= 1) {
                int t2 = __shfl_up_sync(0xffffffffu, w, o);
                if (lane >= o) w += t2;
            }
            wbH[lane] = w;
        }
        __syncthreads();
        int rE = bE + ((wid > 0) ? wbE[wid - 1] : 0) + xE - cE;
        int rH = bH + ((wid > 0) ? wbH[wid - 1] : 0) + xH - cH;
        int totE = wbE[31], totH = wbH[31];

        if (em | hm) {
            int n0 = start + tid * P;
#pragma unroll
            for (int q = 0; q < P; q++) {
                if ((em >> (q * 8)) & 1u) { if (rE < K_EASY) g_idx[rE] = n0 + q; rE++; }
                if ((hm >> (q * 8)) & 1u) { if (rH < K_HARD) g_idx[K_EASY + rH] = n0 + q; rH++; }
            }
        }
        __syncthreads();
        if (tid == 0) { baseE = bE + totE; baseH = bH + totH; }
        __syncthreads();
        if (baseE >= K_EASY && baseH >= K_HARD) break;
    }
    int ne = baseE < K_EASY ? baseE : K_EASY;
    int nh = baseH < K_HARD ? baseH : K_HARD;
    if (tid == 0) { g_ne = ne; g_nh = nh; g_nv = ne + nh; }
    if (tid < AA)
        g_valid[tid] = (unsigned char)((tid < ne) || (tid >= K_EASY && tid < K_EASY + nh));
}

// ---------------- kernel 3: gather + normalize anchor embeddings -----------
__global__ void k_anchors(const float* __restrict__ emb) {
    int s = blockIdx.x;
    int tid = threadIdx.x;
    if (!g_valid[s]) {
        g_anchors[s * DIM + tid] = 0.0f;
        return;
    }
    int n = g_idx[s];
    int b = n >> 14;
    int rem = n & 16383;
    int y = rem >> 7;
    int x = rem & 127;
    float e = emb[((b * DIM + tid) * 128 + y) * 128 + x];
    float v = e * e;
    for (int off = 16; off; off >>= 1) v += __shfl_down_sync(0xffffffffu, v, off);
    __shared__ float ws[4];
    if ((tid & 31) == 0) ws[tid >> 5] = v;
    __syncthreads();
    float tot = ws[0] + ws[1] + ws[2] + ws[3];
    float nrm = sqrtf(tot);
    g_anchors[s * DIM + tid] = e / fmaxf(nrm, 1e-12f);
}

// ---------------- kernel 4: sims GEMM + inline B row norms + fused copy ----
// grid.y 0,1 = GEMM tiles (a0 = y*71); y==2 = memory->out copy (overlapped).
// B row-norms computed inline from the already-loaded B data.
__global__ void __launch_bounds__(256, 2) k_gemm(const float* __restrict__ memory,
                                                 float* __restrict__ out, int write_mem) {
    if (blockIdx.y == 2) {
        // fused memory copy: block bx copies rows [bx*128, bx*128+128)
        if (!write_mem) return;
        int t = threadIdx.x;
        int r = blockIdx.x * 128 + (t >> 1);
        int half = (t & 1) * 64;
        if (r < NROWS) {
            const float4* src = reinterpret_cast<const float4*>(
                memory + (size_t)r * DIM + half);
            float* d = out + 1 + (size_t)r * DIM + half;
#pragma unroll
            for (int q = 0; q < 16; q++) {
                float4 v = src[q];
                d[q * 4 + 0] = v.x; d[q * 4 + 1] = v.y;
                d[q * 4 + 2] = v.z; d[q * 4 + 3] = v.w;
            }
        }
        return;
    }
    __shared__ __align__(16) float As[32][132];
    __shared__ __align__(16) float Bs[32][132];
    __shared__ float rsq[8][132];
    __shared__ float rnsh[128];
    int t = threadIdx.x;
    int tx = t & 15, ty = t >> 4;
    int a0 = blockIdx.y * 71;          // tiles cover rows 0..127 and 71..198
    int n0 = blockIdx.x * 128;

    unsigned long long acc2[8][4];
#pragma unroll
    for (int i = 0; i < 8; i++)
#pragma unroll
        for (int j = 0; j < 4; j++) acc2[i][j] = 0ull;

    float bsq[4] = {0.f, 0.f, 0.f, 0.f};

    for (int k0 = 0; k0 < 128; k0 += 32) {
#pragma unroll
        for (int i = 0; i < 4; i++) {
            int f = t + i * 256;          // 0..1023 float4s
            int row = f >> 3, kq = f & 7;
            float4 v = *reinterpret_cast<const float4*>(
                &g_anchors[(a0 + row) * DIM + k0 + kq * 4]);
            As[kq * 4 + 0][row] = v.x;
            As[kq * 4 + 1][row] = v.y;
            As[kq * 4 + 2][row] = v.z;
            As[kq * 4 + 3][row] = v.w;
        }
#pragma unroll
        for (int i = 0; i < 4; i++) {
            int f = t + i * 256;
            int row = f >> 3, kq = f & 7;
            float4 v = make_float4(0.f, 0.f, 0.f, 0.f);
            if (n0 + row < NROWS)
                v = *reinterpret_cast<const float4*>(
                    &memory[(size_t)(n0 + row) * DIM + k0 + kq * 4]);
            bsq[i] += v.x * v.x + v.y * v.y + v.z * v.z + v.w * v.w;
            Bs[kq * 4 + 0][row] = v.x;
            Bs[kq * 4 + 1][row] = v.y;
            Bs[kq * 4 + 2][row] = v.z;
            Bs[kq * 4 + 3][row] = v.w;
        }
        __syncthreads();
#pragma unroll
        for (int kk = 0; kk < 32; kk++) {
            float4 va0 = *reinterpret_cast<float4*>(&As[kk][ty * 8 + 0]);
            float4 va1 = *reinterpret_cast<float4*>(&As[kk][ty * 8 + 4]);
            ulonglong2 vb0 = *reinterpret_cast<ulonglong2*>(&Bs[kk][tx * 8]);
            ulonglong2 vb1 = *reinterpret_cast<ulonglong2*>(&Bs[kk][tx * 8 + 4]);
            unsigned long long b2[4] = {vb0.x, vb0.y, vb1.x, vb1.y};
            unsigned long long a2[8];
            asm("mov.b64 %0,{%1,%1};" : "=l"(a2[0]) : "r"(__float_as_uint(va0.x)));
            asm("mov.b64 %0,{%1,%1};" : "=l"(a2[1]) : "r"(__float_as_uint(va0.y)));
            asm("mov.b64 %0,{%1,%1};" : "=l"(a2[2]) : "r"(__float_as_uint(va0.z)));
            asm("mov.b64 %0,{%1,%1};" : "=l"(a2[3]) : "r"(__float_as_uint(va0.w)));
            asm("mov.b64 %0,{%1,%1};" : "=l"(a2[4]) : "r"(__float_as_uint(va1.x)));
            asm("mov.b64 %0,{%1,%1};" : "=l"(a2[5]) : "r"(__float_as_uint(va1.y)));
            asm("mov.b64 %0,{%1,%1};" : "=l"(a2[6]) : "r"(__float_as_uint(va1.z)));
            asm("mov.b64 %0,{%1,%1};" : "=l"(a2[7]) : "r"(__float_as_uint(va1.w)));
#pragma unroll
            for (int i = 0; i < 8; i++)
#pragma unroll
                for (int j = 0; j < 4; j++)
                    asm("fma.rn.f32x2 %0, %1, %2, %0;"
                        : "+l"(acc2[i][j]) : "l"(a2[i]), "l"(b2[j]));
        }
        __syncthreads();
    }

    // reduce per-row sum-of-squares, compute reciprocal norms in smem
#pragma unroll
    for (int i = 0; i < 4; i++) {
        int f = t + i * 256;
        int row = f >> 3, kq = f & 7;
        rsq[kq][row] = bsq[i];
    }
    __syncthreads();
    if (t < 128) {
        float s = 0.f;
#pragma unroll
        for (int kq = 0; kq < 8; kq++) s += rsq[kq][t];
        rnsh[t] = 1.0f / fmaxf(sqrtf(s), 1e-8f);
    }
    __syncthreads();

    float rn[8];
#pragma unroll
    for (int j = 0; j < 8; j++) rn[j] = rnsh[tx * 8 + j];
    int skip_below = (blockIdx.y == 1) ? 57 : 0;   // tile-1 rows 0..56 duplicate tile 0
#pragma unroll
    for (int i = 0; i < 8; i++) {
        int lrow = ty * 8 + i;
        if (lrow < skip_below) continue;
        float2 p0 = *reinterpret_cast<float2*>(&acc2[i][0]);
        float2 p1 = *reinterpret_cast<float2*>(&acc2[i][1]);
        float2 p2 = *reinterpret_cast<float2*>(&acc2[i][2]);
        float2 p3 = *reinterpret_cast<float2*>(&acc2[i][3]);
        float4 v0 = make_float4(p0.x * rn[0], p0.y * rn[1], p1.x * rn[2], p1.y * rn[3]);
        float4 v1 = make_float4(p2.x * rn[4], p2.y * rn[5], p3.x * rn[6], p3.y * rn[7]);
        float* dst = &g_sims[(size_t)(a0 + lrow) * NPAD + n0 + tx * 8];
        *reinterpret_cast<float4*>(dst) = v0;
        *reinterpret_cast<float4*>(dst + 4) = v1;
    }
}

// ---------------- kernel 5: select + fused anchor scatter + finalize -------
__global__ void __launch_bounds__(TS) k_select(float* __restrict__ out, int write_mem) {
    int a = blockIdx.x;
    int tid = threadIdx.x;
    int lane = tid & 31;

    if (g_valid[a]) {
        int cls = g_cls;

        // fused anchor scatter (runs after gemm's copy; overwrites copied rows)
        if (write_mem && tid < DIM) {
            int ne = g_ne;
            int w = (a < K_EASY) ? a : (ne + (a - K_EASY));
            out[1 + (((cls - 1) * MEM + w) * DIM) + tid] = g_anchors[a * DIM + tid];
        }

        int cp = cls - 1;
        if (cp < 0) cp = 0;
        if (cp > NC - 2) cp = NC - 2;
        int lo_ex = cp * MEM;

        const float* __restrict__ row = g_sims + (size_t)a * NPAD;

        __shared__ float  pos[1024];
        __shared__ double pre[1025];
        __shared__ double wbd[16];
        __shared__ unsigned wbu[16];
        __shared__ unsigned hist[2048];
        __shared__ unsigned cand[CAP];
        __shared__ unsigned s_cnt;
        __shared__ unsigned s_bin, s_kth;
        __shared__ double rsum[16];
        __shared__ int    rcnt[16];

        if (tid == 0) s_cnt = 0;
        for (int i = tid; i < 1024; i += TS)
            pos[i] = (i < MEM) ? row[lo_ex + i] : __int_as_float(0x7F800000);
#pragma unroll
        for (int q = 0; q < 4; q++) hist[tid + q * TS] = 0u;
        __syncthreads();

        // bitonic sort ascending (1024)
        for (unsigned k = 2; k <= 1024; k <<= 1) {
            for (unsigned j = k >> 1; j > 0; j >>= 1) {
                for (unsigned i = tid; i < 1024; i += TS) {
                    unsigned ixj = i ^ j;
                    if (ixj > i) {
                        float va = pos[i], vb = pos[ixj];
                        bool up = ((i & k) == 0);
                        if ((va > vb) == up) { pos[i] = vb; pos[ixj] = va; }
                    }
                }
                __syncthreads();
            }
        }

        // prefix sums of sorted positives (2 elems/thread, shuffle scan)
        {
            double s = 0.0;
#pragma unroll
            for (int q = 0; q < 2; q++) {
                int idx = tid * 2 + q;
                if (idx < MEM) s += (double)pos[idx];
            }
            double run = blk_exscan_d(s, tid, wbd);
#pragma unroll
            for (int q = 0; q < 2; q++) {
                int idx = tid * 2 + q;
                if (idx < MEM) { pre[idx] = run; run += (double)pos[idx]; }
            }
            if (tid * 2 <= MEM - 1 && tid * 2 + 1 >= MEM - 1) pre[MEM] = run;
            __syncthreads();
        }

        // scan 1: coarse 11-bit histogram, 8-wide batched loads (40 iters)
        for (int it = 0; it < 40; it += 8) {
            float vals[8];
#pragma unroll
            for (int q = 0; q < 8; q++) {
                int j = tid + (it + q) * TS;
                int i = j + ((j >= lo_ex) ? MEM : 0);
                vals[q] = (j < NEGS) ? __ldg(row + i) : 0.0f;
            }
#pragma unroll
            for (int q = 0; q < 8; q++) {
                int j = tid + (it + q) * TS;
                bool valid = (j < NEGS);
                unsigned act = __ballot_sync(0xffffffffu, valid);
                if (valid) {
                    unsigned u = fmono(vals[q]);
                    unsigned bin = u >> 21;
                    unsigned m = __match_any_sync(act, bin);
                    if ((lane == (__ffs(m) - 1)))
                        atomicAdd(&hist[bin], (unsigned)__popc(m));
                }
            }
        }
        __syncthreads();

        unsigned kth = MEM;
        {
            unsigned ls = 0;
            int base = 2047 - tid * 4;
#pragma unroll
            for (int q = 0; q < 4; q++) ls += hist[base - q];
            unsigned excl = blk_exscan_u(ls, tid, wbu);
            if (excl < kth && excl + ls >= kth) {
                unsigned run = excl;
#pragma unroll
                for (int q = 0; q < 4; q++) {
                    unsigned h = hist[base - q];
                    if (run + h >= kth) { s_bin = (unsigned)(base - q); s_kth = kth - run; break; }
                    run += h;
                }
            }
            __syncthreads();
        }
        unsigned b0 = s_bin;
        kth = s_kth;
        __syncthreads();

        // scan 2: batched loads; accumulate above-bin, collect boundary bin
        double lsum = 0.0;
        int lcnt = 0;
        for (int it = 0; it < 40; it += 8) {
            float vals[8];
#pragma unroll
            for (int q = 0; q < 8; q++) {
                int j = tid + (it + q) * TS;
                int i = j + ((j >= lo_ex) ? MEM : 0);
                vals[q] = (j < NEGS) ? __ldg(row + i) : -__int_as_float(0x7F800000);
            }
#pragma unroll
            for (int q = 0; q < 8; q++) {
                int j = tid + (it + q) * TS;
                if (j >= NEGS) continue;
                float n = vals[q];
                unsigned u = fmono(n);
                unsigned bin = u >> 21;
                if (bin > b0) {
                    float thr = n - MARGIN;
                    int lo = 0, hi = MEM;
                    while (lo < hi) {
                        int mid = (lo + hi) >> 1;
                        if (pos[mid] <= thr) lo = mid + 1; else hi = mid;
                    }
                    int cntp = MEM - lo;
                    lsum += (pre[MEM] - pre[lo]) + (double)cntp * ((double)MARGIN - (double)n);
                    lcnt++;
                } else if (bin == b0) {
                    unsigned idx = atomicAdd(&s_cnt, 1u);
                    if (idx < CAP) cand[idx] = u;
                }
            }
        }
        __syncthreads();
        int ncand = (int)min(s_cnt, (unsigned)CAP);

        // refinement pass 1: bits [20:10] on candidates in smem
        unsigned prefix = b0 << 21;
#pragma unroll
        for (int q = 0; q < 4; q++) hist[tid + q * TS] = 0u;
        __syncthreads();
        for (int i = tid; i < ncand; i += TS)
            atomicAdd(&hist[(cand[i] >> 10) & 2047u], 1u);
        __syncthreads();
        {
            unsigned ls = 0;
            int base = 2047 - tid * 4;
#pragma unroll
            for (int q = 0; q < 4; q++) ls += hist[base - q];
            unsigned excl = blk_exscan_u(ls, tid, wbu);
            if (excl < kth && excl + ls >= kth) {
                unsigned run = excl;
#pragma unroll
                for (int q = 0; q < 4; q++) {
                    unsigned h = hist[base - q];
                    if (run + h >= kth) { s_bin = (unsigned)(base - q); s_kth = kth - run; break; }
                    run += h;
                }
            }
            __syncthreads();
        }
        prefix |= s_bin << 10;
        kth = s_kth;
        __syncthreads();

        // refinement pass 2: bits [9:0]
#pragma unroll
        for (int q = 0; q < 2; q++) hist[tid + q * TS] = 0u;
        __syncthreads();
        for (int i = tid; i < ncand; i += TS) {
            unsigned u = cand[i];
            if ((u >> 10) == (prefix >> 10)) atomicAdd(&hist[u & 1023u], 1u);
        }
        __syncthreads();
        {
            unsigned ls = 0;
            int base = 1023 - tid * 2;
#pragma unroll
            for (int q = 0; q < 2; q++) ls += hist[base - q];
            unsigned excl = blk_exscan_u(ls, tid, wbu);
            if (excl < kth && excl + ls >= kth) {
                unsigned run = excl;
#pragma unroll
                for (int q = 0; q < 2; q++) {
                    unsigned h = hist[base - q];
                    if (run + h >= kth) { s_bin = (unsigned)(base - q); break; }
                    run += h;
                }
            }
            __syncthreads();
        }
        prefix |= s_bin;
        float tval = fmono_inv(prefix);

        for (int i = tid; i < ncand; i += TS) {
            unsigned u = cand[i];
            if (u > prefix) {
                float n = fmono_inv(u);
                float thr = n - MARGIN;
                int lo = 0, hi = MEM;
                while (lo < hi) {
                    int mid = (lo + hi) >> 1;
                    if (pos[mid] <= thr) lo = mid + 1; else hi = mid;
                }
                int cntp = MEM - lo;
                lsum += (pre[MEM] - pre[lo]) + (double)cntp * ((double)MARGIN - (double)n);
                lcnt++;
            }
        }

        for (int off = 16; off; off >>= 1) {
            lsum += __shfl_down_sync(0xffffffffu, lsum, off);
            lcnt += __shfl_down_sync(0xffffffffu, lcnt, off);
        }
        if (lane == 0) { rsum[tid >> 5] = lsum; rcnt[tid >> 5] = lcnt; }
        __syncthreads();
        if (tid == 0) {
            double tot = 0.0; int cnt = 0;
#pragma unroll
            for (int w = 0; w < 16; w++) { tot += rsum[w]; cnt += rcnt[w]; }
            float thr = tval - MARGIN;
            int lo = 0, hi = MEM;
            while (lo < hi) {
                int mid = (lo + hi) >> 1;
                if (pos[mid] <= thr) lo = mid + 1; else hi = mid;
            }
            int cntp = MEM - lo;
            double gt = (pre[MEM] - pre[lo]) + (double)cntp * ((double)MARGIN - (double)tval);
            tot += (double)(MEM - cnt) * gt;
            atomicAdd(&g_loss, tot * 1e-6);
        }
    }

    // fused finalize: last block to finish writes the loss
    if (tid == 0) {
        __threadfence();
        int d = atomicAdd(&g_done, 1);
        if (d == AA - 1) {
            int nv = g_nv;
            double denom = (nv > 1) ? (double)nv : 1.0;
            out[0] = (float)(g_loss / denom);
        }
    }
}

// ---------------- launch ----------------
extern "C" void kernel_launch(void* const* d_in, const int* in_sizes, int n_in,
                              void* d_out, int out_size) {
    const float* preds  = (const float*)d_in[0];
    const float* emb    = (const float*)d_in[1];
    const int*   wsss   = (const int*)d_in[2];
    const int*   fsss   = (const int*)d_in[3];
    const float* memory = (const float*)d_in[4];
    float* out = (float*)d_out;

    int write_mem = (out_size >= 1 + (NC - 1) * MEM * DIM) ? 1 : 0;

    k_prep<<<512, 256>>>(preds, wsss, fsss);
    k_pick<<<1, 1024>>>();
    k_anchors<<<AA, DIM>>>(emb);
    dim3 ggrid(NPAD / 128, 3);
    k_gemm<<<ggrid, 256>>>(memory, out, write_mem);
    k_select<<<AA, TS>>>(out, write_mem);
}

// round 15
// speedup vs baseline: 1.0536x; 1.0536x over previous
#include <cuda_runtime.h>
#include <cuda_bf16.h>
#include <math.h>

// ---------------- problem constants ----------------
#define NC      21
#define MEM     1000
#define DIM     128
#define NPIX    131072      // 8 * 128 * 128
#define K_EASY  39          // int(200 * (1 - 0.8)) with fp64 rounding
#define K_HARD  160
#define AA      199         // K_EASY + K_HARD
#define NROWS   20000       // (NC-1) * MEM
#define NPAD    20096       // 157 * 128
#define MPAD    256
#define MARGIN  0.2f
#define NEGS    (NROWS - MEM)   // 19000
#define CAP     6144
#define TS      512             // k_select threads

// ---------------- scratch (device globals; no allocation allowed) --------
__device__ __align__(16) unsigned char g_sw[NPIX];
__device__ __align__(16) unsigned char g_sp[NPIX];
__device__ __align__(16) unsigned char g_fg[NPIX];
__device__ int           g_cls;
__device__ int           g_idx[AA];
__device__ unsigned char g_valid[AA];
__device__ int           g_ne, g_nh, g_nv;
__device__ int           g_done;
__device__ float         g_anchors[MPAD * DIM];
__device__ float         g_rnorm[NPAD];
__device__ float         g_sims[MPAD * NPAD];
__device__ double        g_loss;

// ---------------- helpers ----------------
__device__ __forceinline__ unsigned fmono(float f) {
    unsigned u = __float_as_uint(f);
    return (u & 0x80000000u) ? ~u : (u | 0x80000000u);
}
__device__ __forceinline__ float fmono_inv(unsigned u) {
    return (u & 0x80000000u) ? __uint_as_float(u & 0x7FFFFFFFu)
                             : __uint_as_float(~u);
}

// block-wide EXCLUSIVE scans (two-level shuffle), for TS=512 (16 warps)
__device__ __forceinline__ unsigned blk_exscan_u(unsigned v, int tid, unsigned* wb) {
    __syncthreads();                       // protect wb reuse
    int lane = tid & 31, wid = tid >> 5;
    unsigned x = v;
#pragma unroll
    for (int o = 1; o < 32; o <<= 1) {
        unsigned t = __shfl_up_sync(0xffffffffu, x, o);
        if (lane >= o) x += t;
    }
    if (lane == 31) wb[wid] = x;
    __syncthreads();
    if (tid < 16) {
        unsigned w = wb[tid];
#pragma unroll
        for (int o = 1; o < 16; o <<= 1) {
            unsigned t = __shfl_up_sync(0x0000ffffu, w, o);
            if (tid >= o) w += t;
        }
        wb[tid] = w;
    }
    __syncthreads();
    unsigned off = (wid > 0) ? wb[wid - 1] : 0u;
    return off + x - v;
}
__device__ __forceinline__ double blk_exscan_d(double v, int tid, double* wb) {
    __syncthreads();
    int lane = tid & 31, wid = tid >> 5;
    double x = v;
#pragma unroll
    for (int o = 1; o < 32; o <<= 1) {
        double t = __shfl_up_sync(0xffffffffu, x, o);
        if (lane >= o) x += t;
    }
    if (lane == 31) wb[wid] = x;
    __syncthreads();
    if (tid < 16) {
        double w = wb[tid];
#pragma unroll
        for (int o = 1; o < 16; o <<= 1) {
            double t = __shfl_up_sync(0x0000ffffu, w, o);
            if (tid >= o) w += t;
        }
        wb[tid] = w;
    }
    __syncthreads();
    double off = (wid > 0) ? wb[wid - 1] : 0.0;
    return off + x - v;
}

// ---------------- kernel 1: flags/argmax + mem row norms + mem copy --------
__global__ void k_prep(const float* __restrict__ preds,
                       const int* __restrict__ wsss,
                       const int* __restrict__ fsss,
                       const float* __restrict__ memory,
                       float* __restrict__ out, int write_mem) {
    int bid = blockIdx.x;
    int tid = threadIdx.x;
    if (bid < 512) {
        int n = bid * 256 + tid;
        int b = n >> 14;
        int rem = n & 16383;
        int y = rem >> 7;
        int x = rem & 127;
        int Y = y * 4, X = x * 4;
        int gidx = (b * 512 + Y) * 512 + X;
        int sw = wsss[gidx];
        int sf = fsss[gidx];

        const float* p = preds + ((long long)b * NC) * 262144 + (long long)Y * 512 + X;
        float best = __ldg(p);
        int bi = 0;
#pragma unroll
        for (int c = 1; c < NC; c++) {
            float v = __ldg(p + (long long)c * 262144);
            if (v > best) { best = v; bi = c; }
        }
        g_sw[n] = (unsigned char)sw;
        g_sp[n] = (unsigned char)bi;
        g_fg[n] = (unsigned char)((sf != 0) && (sf != 255));
    } else {
        int r = (bid - 512) * 8 + (tid >> 5);  // one warp per row
        if (r >= NPAD) return;
        int lane = tid & 31;
        float s = 0.0f;
        if (r < NROWS) {
            float4 v = *reinterpret_cast<const float4*>(memory + (size_t)r * DIM + lane * 4);
            s = v.x * v.x + v.y * v.y + v.z * v.z + v.w * v.w;
            if (write_mem) {  // fused copy (scalar: dest +1 misaligned for vec)
                float* d = out + 1 + (size_t)r * DIM + lane * 4;
                d[0] = v.x; d[1] = v.y; d[2] = v.z; d[3] = v.w;
            }
        }
        for (int off = 16; off; off >>= 1) s += __shfl_down_sync(0xffffffffu, s, off);
        if (lane == 0)
            g_rnorm[r] = (r < NROWS) ? (1.0f / fmaxf(sqrtf(s), 1e-8f)) : 0.0f;
    }
}

// ---------------- kernel 2: cls + ordered pick (vector loads, shuffle scan) -
__global__ void k_pick() {
    const int T = 1024, P = 4, CH = T * P;   // 4096 pixels per chunk
    __shared__ int wbE[32], wbH[32];
    __shared__ int baseE, baseH;
    __shared__ int s_cls;
    int tid = threadIdx.x;
    int lane = tid & 31, wid = tid >> 5;
    if (tid == 0) { baseE = 0; baseH = 0; s_cls = 255; g_loss = 0.0; g_done = 0; }
    __syncthreads();

    // phase A: min valid label over g_sw
    {
        const uint4* sw4 = reinterpret_cast<const uint4*>(g_sw);
        unsigned m4 = 0xFFFFFFFFu;
#pragma unroll
        for (int q = 0; q < 8; q++) {
            uint4 v = sw4[tid * 8 + q];
            unsigned a = v.x | __vcmpeq4(v.x, 0u);
            unsigned b = v.y | __vcmpeq4(v.y, 0u);
            unsigned c = v.z | __vcmpeq4(v.z, 0u);
            unsigned d = v.w | __vcmpeq4(v.w, 0u);
            m4 = __vminu4(m4, __vminu4(__vminu4(a, b), __vminu4(c, d)));
        }
        unsigned m = min(min(m4 & 255u, (m4 >> 8) & 255u),
                         min((m4 >> 16) & 255u, (m4 >> 24) & 255u));
        for (int off = 16; off; off >>= 1)
            m = min(m, __shfl_down_sync(0xffffffffu, m, off));
        if (lane == 0) atomicMin(&s_cls, (int)m);
    }
    __syncthreads();
    int cls = (s_cls <= NC - 1) ? s_cls : NC;
    if (tid == 0) g_cls = cls;
    unsigned cls4 = (unsigned)cls * 0x01010101u;
    const unsigned one4 = 0x01010101u;

    // phase B: ordered pick, 4 pixels per thread per chunk via uint loads
    for (int start = 0; start < NPIX; start += CH) {
        int bE = baseE, bH = baseH;
        int widx = (start >> 2) + tid;
        unsigned sw = reinterpret_cast<const unsigned*>(g_sw)[widx];
        unsigned sp = reinterpret_cast<const unsigned*>(g_sp)[widx];
        unsigned fg = reinterpret_cast<const unsigned*>(g_fg)[widx];
        unsigned ancm = __vcmpeq4(sw, cls4) & __vcmpeq4(fg, one4);
        unsigned spm  = __vcmpeq4(sp, cls4);
        unsigned em = ancm & spm;
        unsigned hm = ancm & ~spm;
        int cE = __popc(em) >> 3;
        int cH = __popc(hm) >> 3;

        // two-level exclusive shuffle scan over 1024 threads
        int xE = cE, xH = cH;
#pragma unroll
        for (int o = 1; o < 32; o <<= 1) {
            int tE = __shfl_up_sync(0xffffffffu, xE, o);
            int tH = __shfl_up_sync(0xffffffffu, xH, o);
            if (lane >= o) { xE += tE; xH += tH; }
        }
        if (lane == 31) { wbE[wid] = xE; wbH[wid] = xH; }
        __syncthreads();
        if (wid == 0) {
            int w = wbE[lane];
#pragma unroll
            for (int o = 1; o < 32; o <<= 1) {
                int t2 = __shfl_up_sync(0xffffffffu, w, o);
                if (lane >= o) w += t2;
            }
            wbE[lane] = w;
        } else if (wid == 1) {
            int w = wbH[lane];
#pragma unroll
            for (int o = 1; o < 32; o <<= 1) {
                int t2 = __shfl_up_sync(0xffffffffu, w, o);
                if (lane >= o) w += t2;
            }
            wbH[lane] = w;
        }
        __syncthreads();
        int rE = bE + ((wid > 0) ? wbE[wid - 1] : 0) + xE - cE;
        int rH = bH + ((wid > 0) ? wbH[wid - 1] : 0) + xH - cH;
        int totE = wbE[31], totH = wbH[31];

        if (em | hm) {
            int n0 = start + tid * P;
#pragma unroll
            for (int q = 0; q < P; q++) {
                if ((em >> (q * 8)) & 1u) { if (rE < K_EASY) g_idx[rE] = n0 + q; rE++; }
                if ((hm >> (q * 8)) & 1u) { if (rH < K_HARD) g_idx[K_EASY + rH] = n0 + q; rH++; }
            }
        }
        __syncthreads();
        if (tid == 0) { baseE = bE + totE; baseH = bH + totH; }
        __syncthreads();
        if (baseE >= K_EASY && baseH >= K_HARD) break;
    }
    int ne = baseE < K_EASY ? baseE : K_EASY;
    int nh = baseH < K_HARD ? baseH : K_HARD;
    if (tid == 0) { g_ne = ne; g_nh = nh; g_nv = ne + nh; }
    if (tid < AA)
        g_valid[tid] = (unsigned char)((tid < ne) || (tid >= K_EASY && tid < K_EASY + nh));
}

// ---------------- kernel 3: gather + normalize anchor embeddings -----------
__global__ void k_anchors(const float* __restrict__ emb) {
    int s = blockIdx.x;
    int tid = threadIdx.x;
    if (!g_valid[s]) {
        g_anchors[s * DIM + tid] = 0.0f;
        return;
    }
    int n = g_idx[s];
    int b = n >> 14;
    int rem = n & 16383;
    int y = rem >> 7;
    int x = rem & 127;
    float e = emb[((b * DIM + tid) * 128 + y) * 128 + x];
    float v = e * e;
    for (int off = 16; off; off >>= 1) v += __shfl_down_sync(0xffffffffu, v, off);
    __shared__ float ws[4];
    if ((tid & 31) == 0) ws[tid >> 5] = v;
    __syncthreads();
    float tot = ws[0] + ws[1] + ws[2] + ws[3];
    float nrm = sqrtf(tot);
    g_anchors[s * DIM + tid] = e / fmaxf(nrm, 1e-12f);
}

// ---------------- kernel 4: sims GEMM (128x128x32, 8x8/thread, f32x2) ------
// A stored UNSPLATTED in smem; splat in registers via mov.b64 (idle ALU pipe).
// grid.y: 0,1 = GEMM tiles (a0 = y*71, overlap rows identical), 2 = scatter.
// Tile 1 skips stores for rows 0..56 (duplicates of tile 0's rows 71..127).
__global__ void __launch_bounds__(256, 2) k_gemm(const float* __restrict__ memory,
                                                 float* __restrict__ out, int write_mem) {
    if (blockIdx.y == 2) {
        if (!write_mem) return;
        int bx = blockIdx.x;
        if (bx >= 100) return;
        int t = threadIdx.x;
        int s = bx * 2 + (t >> 7);
        int lane = t & 127;
        if (s >= AA || !g_valid[s]) return;
        int cls = g_cls;
        int ne = g_ne;
        int w = (s < K_EASY) ? s : (ne + (s - K_EASY));
        out[1 + (((cls - 1) * MEM + w) * DIM) + lane] = g_anchors[s * DIM + lane];
        return;
    }
    __shared__ __align__(16) float As[32][132];
    __shared__ __align__(16) float Bs[32][132];
    int t = threadIdx.x;
    int tx = t & 15, ty = t >> 4;
    int a0 = blockIdx.y * 71;          // tiles cover rows 0..127 and 71..198
    int n0 = blockIdx.x * 128;

    unsigned long long acc2[8][4];
#pragma unroll
    for (int i = 0; i < 8; i++)
#pragma unroll
        for (int j = 0; j < 4; j++) acc2[i][j] = 0ull;

    for (int k0 = 0; k0 < 128; k0 += 32) {
#pragma unroll
        for (int i = 0; i < 4; i++) {
            int f = t + i * 256;          // 0..1023 float4s
            int row = f >> 3, kq = f & 7;
            float4 v = *reinterpret_cast<const float4*>(
                &g_anchors[(a0 + row) * DIM + k0 + kq * 4]);
            As[kq * 4 + 0][row] = v.x;
            As[kq * 4 + 1][row] = v.y;
            As[kq * 4 + 2][row] = v.z;
            As[kq * 4 + 3][row] = v.w;
        }
#pragma unroll
        for (int i = 0; i < 4; i++) {
            int f = t + i * 256;
            int row = f >> 3, kq = f & 7;
            float4 v = make_float4(0.f, 0.f, 0.f, 0.f);
            if (n0 + row < NROWS)
                v = *reinterpret_cast<const float4*>(
                    &memory[(size_t)(n0 + row) * DIM + k0 + kq * 4]);
            Bs[kq * 4 + 0][row] = v.x;
            Bs[kq * 4 + 1][row] = v.y;
            Bs[kq * 4 + 2][row] = v.z;
            Bs[kq * 4 + 3][row] = v.w;
        }
        __syncthreads();
#pragma unroll
        for (int kk = 0; kk < 32; kk++) {
            float4 va0 = *reinterpret_cast<float4*>(&As[kk][ty * 8 + 0]);
            float4 va1 = *reinterpret_cast<float4*>(&As[kk][ty * 8 + 4]);
            ulonglong2 vb0 = *reinterpret_cast<ulonglong2*>(&Bs[kk][tx * 8]);
            ulonglong2 vb1 = *reinterpret_cast<ulonglong2*>(&Bs[kk][tx * 8 + 4]);
            unsigned long long b2[4] = {vb0.x, vb0.y, vb1.x, vb1.y};
            unsigned long long a2[8];
            asm("mov.b64 %0,{%1,%1};" : "=l"(a2[0]) : "r"(__float_as_uint(va0.x)));
            asm("mov.b64 %0,{%1,%1};" : "=l"(a2[1]) : "r"(__float_as_uint(va0.y)));
            asm("mov.b64 %0,{%1,%1};" : "=l"(a2[2]) : "r"(__float_as_uint(va0.z)));
            asm("mov.b64 %0,{%1,%1};" : "=l"(a2[3]) : "r"(__float_as_uint(va0.w)));
            asm("mov.b64 %0,{%1,%1};" : "=l"(a2[4]) : "r"(__float_as_uint(va1.x)));
            asm("mov.b64 %0,{%1,%1};" : "=l"(a2[5]) : "r"(__float_as_uint(va1.y)));
            asm("mov.b64 %0,{%1,%1};" : "=l"(a2[6]) : "r"(__float_as_uint(va1.z)));
            asm("mov.b64 %0,{%1,%1};" : "=l"(a2[7]) : "r"(__float_as_uint(va1.w)));
#pragma unroll
            for (int i = 0; i < 8; i++)
#pragma unroll
                for (int j = 0; j < 4; j++)
                    asm("fma.rn.f32x2 %0, %1, %2, %0;"
                        : "+l"(acc2[i][j]) : "l"(a2[i]), "l"(b2[j]));
        }
        __syncthreads();
    }

    float rn[8];
#pragma unroll
    for (int j = 0; j < 8; j++) rn[j] = g_rnorm[n0 + tx * 8 + j];
    int skip_below = (blockIdx.y == 1) ? 57 : 0;   // tile-1 rows 0..56 duplicate tile 0
#pragma unroll
    for (int i = 0; i < 8; i++) {
        int lrow = ty * 8 + i;
        if (lrow < skip_below) continue;
        float2 p0 = *reinterpret_cast<float2*>(&acc2[i][0]);
        float2 p1 = *reinterpret_cast<float2*>(&acc2[i][1]);
        float2 p2 = *reinterpret_cast<float2*>(&acc2[i][2]);
        float2 p3 = *reinterpret_cast<float2*>(&acc2[i][3]);
        float4 v0 = make_float4(p0.x * rn[0], p0.y * rn[1], p1.x * rn[2], p1.y * rn[3]);
        float4 v1 = make_float4(p2.x * rn[4], p2.y * rn[5], p3.x * rn[6], p3.y * rn[7]);
        float* dst = &g_sims[(size_t)(a0 + lrow) * NPAD + n0 + tx * 8];
        *reinterpret_cast<float4*>(dst) = v0;
        *reinterpret_cast<float4*>(dst + 4) = v1;
    }
}

// ---------------- kernel 5: two-scan top-1000 select + analytic pair sum ----
// TS=512 threads; all prefix sums via two-level shuffle scans (2 barriers each)
__global__ void __launch_bounds__(TS) k_select(float* __restrict__ out) {
    int a = blockIdx.x;
    int tid = threadIdx.x;
    int lane = tid & 31;

    if (g_valid[a]) {
        int cls = g_cls;
        int cp = cls - 1;
        if (cp < 0) cp = 0;
        if (cp > NC - 2) cp = NC - 2;
        int lo_ex = cp * MEM;

        const float* __restrict__ row = g_sims + (size_t)a * NPAD;

        __shared__ float  pos[1024];
        __shared__ double pre[1025];
        __shared__ double wbd[16];
        __shared__ unsigned wbu[16];
        __shared__ unsigned hist[2048];
        __shared__ unsigned cand[CAP];
        __shared__ unsigned s_cnt;
        __shared__ unsigned s_bin, s_kth;
        __shared__ double rsum[16];
        __shared__ int    rcnt[16];

        if (tid == 0) s_cnt = 0;
        for (int i = tid; i < 1024; i += TS)
            pos[i] = (i < MEM) ? row[lo_ex + i] : __int_as_float(0x7F800000);
#pragma unroll
        for (int q = 0; q < 4; q++) hist[tid + q * TS] = 0u;
        __syncthreads();

        // bitonic sort ascending (1024)
        for (unsigned k = 2; k <= 1024; k <<= 1) {
            for (unsigned j = k >> 1; j > 0; j >>= 1) {
                for (unsigned i = tid; i < 1024; i += TS) {
                    unsigned ixj = i ^ j;
                    if (ixj > i) {
                        float va = pos[i], vb = pos[ixj];
                        bool up = ((i & k) == 0);
                        if ((va > vb) == up) { pos[i] = vb; pos[ixj] = va; }
                    }
                }
                __syncthreads();
            }
        }

        // prefix sums of sorted positives (2 elems/thread, shuffle scan)
        {
            double s = 0.0;
#pragma unroll
            for (int q = 0; q < 2; q++) {
                int idx = tid * 2 + q;
                if (idx < MEM) s += (double)pos[idx];
            }
            double run = blk_exscan_d(s, tid, wbd);
#pragma unroll
            for (int q = 0; q < 2; q++) {
                int idx = tid * 2 + q;
                if (idx < MEM) { pre[idx] = run; run += (double)pos[idx]; }
            }
            if (tid * 2 <= MEM - 1 && tid * 2 + 1 >= MEM - 1) pre[MEM] = run;
            __syncthreads();
        }

        // scan 1: coarse 11-bit histogram, 8-wide batched loads (40 iters)
        for (int it = 0; it < 40; it += 8) {
            float vals[8];
#pragma unroll
            for (int q = 0; q < 8; q++) {
                int j = tid + (it + q) * TS;
                int i = j + ((j >= lo_ex) ? MEM : 0);
                vals[q] = (j < NEGS) ? __ldg(row + i) : 0.0f;
            }
#pragma unroll
            for (int q = 0; q < 8; q++) {
                int j = tid + (it + q) * TS;
                bool valid = (j < NEGS);
                unsigned act = __ballot_sync(0xffffffffu, valid);
                if (valid) {
                    unsigned u = fmono(vals[q]);
                    unsigned bin = u >> 21;
                    unsigned m = __match_any_sync(act, bin);
                    if ((lane == (__ffs(m) - 1)))
                        atomicAdd(&hist[bin], (unsigned)__popc(m));
                }
            }
        }
        __syncthreads();

        unsigned kth = MEM;
        {
            unsigned ls = 0;
            int base = 2047 - tid * 4;
#pragma unroll
            for (int q = 0; q < 4; q++) ls += hist[base - q];
            unsigned excl = blk_exscan_u(ls, tid, wbu);
            if (excl < kth && excl + ls >= kth) {
                unsigned run = excl;
#pragma unroll
                for (int q = 0; q < 4; q++) {
                    unsigned h = hist[base - q];
                    if (run + h >= kth) { s_bin = (unsigned)(base - q); s_kth = kth - run; break; }
                    run += h;
                }
            }
            __syncthreads();
        }
        unsigned b0 = s_bin;
        kth = s_kth;
        __syncthreads();

        // scan 2: batched loads; accumulate above-bin, collect boundary bin
        double lsum = 0.0;
        int lcnt = 0;
        for (int it = 0; it < 40; it += 8) {
            float vals[8];
#pragma unroll
            for (int q = 0; q < 8; q++) {
                int j = tid + (it + q) * TS;
                int i = j + ((j >= lo_ex) ? MEM : 0);
                vals[q] = (j < NEGS) ? __ldg(row + i) : -__int_as_float(0x7F800000);
            }
#pragma unroll
            for (int q = 0; q < 8; q++) {
                int j = tid + (it + q) * TS;
                if (j >= NEGS) continue;
                float n = vals[q];
                unsigned u = fmono(n);
                unsigned bin = u >> 21;
                if (bin > b0) {
                    float thr = n - MARGIN;
                    int lo = 0, hi = MEM;
                    while (lo < hi) {
                        int mid = (lo + hi) >> 1;
                        if (pos[mid] <= thr) lo = mid + 1; else hi = mid;
                    }
                    int cntp = MEM - lo;
                    lsum += (pre[MEM] - pre[lo]) + (double)cntp * ((double)MARGIN - (double)n);
                    lcnt++;
                } else if (bin == b0) {
                    unsigned idx = atomicAdd(&s_cnt, 1u);
                    if (idx < CAP) cand[idx] = u;
                }
            }
        }
        __syncthreads();
        int ncand = (int)min(s_cnt, (unsigned)CAP);

        // refinement pass 1: bits [20:10] on candidates in smem
        unsigned prefix = b0 << 21;
#pragma unroll
        for (int q = 0; q < 4; q++) hist[tid + q * TS] = 0u;
        __syncthreads();
        for (int i = tid; i < ncand; i += TS)
            atomicAdd(&hist[(cand[i] >> 10) & 2047u], 1u);
        __syncthreads();
        {
            unsigned ls = 0;
            int base = 2047 - tid * 4;
#pragma unroll
            for (int q = 0; q < 4; q++) ls += hist[base - q];
            unsigned excl = blk_exscan_u(ls, tid, wbu);
            if (excl < kth && excl + ls >= kth) {
                unsigned run = excl;
#pragma unroll
                for (int q = 0; q < 4; q++) {
                    unsigned h = hist[base - q];
                    if (run + h >= kth) { s_bin = (unsigned)(base - q); s_kth = kth - run; break; }
                    run += h;
                }
            }
            __syncthreads();
        }
        prefix |= s_bin << 10;
        kth = s_kth;
        __syncthreads();

        // refinement pass 2: bits [9:0]
#pragma unroll
        for (int q = 0; q < 2; q++) hist[tid + q * TS] = 0u;
        __syncthreads();
        for (int i = tid; i < ncand; i += TS) {
            unsigned u = cand[i];
            if ((u >> 10) == (prefix >> 10)) atomicAdd(&hist[u & 1023u], 1u);
        }
        __syncthreads();
        {
            unsigned ls = 0;
            int base = 1023 - tid * 2;
#pragma unroll
            for (int q = 0; q < 2; q++) ls += hist[base - q];
            unsigned excl = blk_exscan_u(ls, tid, wbu);
            if (excl < kth && excl + ls >= kth) {
                unsigned run = excl;
#pragma unroll
                for (int q = 0; q < 2; q++) {
                    unsigned h = hist[base - q];
                    if (run + h >= kth) { s_bin = (unsigned)(base - q); break; }
                    run += h;
                }
            }
            __syncthreads();
        }
        prefix |= s_bin;
        float tval = fmono_inv(prefix);

        for (int i = tid; i < ncand; i += TS) {
            unsigned u = cand[i];
            if (u > prefix) {
                float n = fmono_inv(u);
                float thr = n - MARGIN;
                int lo = 0, hi = MEM;
                while (lo < hi) {
                    int mid = (lo + hi) >> 1;
                    if (pos[mid] <= thr) lo = mid + 1; else hi = mid;
                }
                int cntp = MEM - lo;
                lsum += (pre[MEM] - pre[lo]) + (double)cntp * ((double)MARGIN - (double)n);
                lcnt++;
            }
        }

        for (int off = 16; off; off >>= 1) {
            lsum += __shfl_down_sync(0xffffffffu, lsum, off);
            lcnt += __shfl_down_sync(0xffffffffu, lcnt, off);
        }
        if (lane == 0) { rsum[tid >> 5] = lsum; rcnt[tid >> 5] = lcnt; }
        __syncthreads();
        if (tid == 0) {
            double tot = 0.0; int cnt = 0;
#pragma unroll
            for (int w = 0; w < 16; w++) { tot += rsum[w]; cnt += rcnt[w]; }
            float thr = tval - MARGIN;
            int lo = 0, hi = MEM;
            while (lo < hi) {
                int mid = (lo + hi) >> 1;
                if (pos[mid] <= thr) lo = mid + 1; else hi = mid;
            }
            int cntp = MEM - lo;
            double gt = (pre[MEM] - pre[lo]) + (double)cntp * ((double)MARGIN - (double)tval);
            tot += (double)(MEM - cnt) * gt;
            atomicAdd(&g_loss, tot * 1e-6);
        }
    }

    // fused finalize: last block to finish writes the loss
    if (tid == 0) {
        __threadfence();
        int d = atomicAdd(&g_done, 1);
        if (d == AA - 1) {
            int nv = g_nv;
            double denom = (nv > 1) ? (double)nv : 1.0;
            out[0] = (float)(g_loss / denom);
        }
    }
}

// ---------------- launch ----------------
extern "C" void kernel_launch(void* const* d_in, const int* in_sizes, int n_in,
                              void* d_out, int out_size) {
    const float* preds  = (const float*)d_in[0];
    const float* emb    = (const float*)d_in[1];
    const int*   wsss   = (const int*)d_in[2];
    const int*   fsss   = (const int*)d_in[3];
    const float* memory = (const float*)d_in[4];
    float* out = (float*)d_out;

    int write_mem = (out_size >= 1 + (NC - 1) * MEM * DIM) ? 1 : 0;

    k_prep<<<512 + (NPAD + 7) / 8, 256>>>(preds, wsss, fsss, memory, out, write_mem);
    k_pick<<<1, 1024>>>();
    k_anchors<<<AA, DIM>>>(emb);
    dim3 ggrid(NPAD / 128, 3);
    k_gemm<<<ggrid, 256>>>(memory, out, write_mem);
    k_select<<<AA, TS>>>(out);
}